// round 7
// baseline (speedup 1.0000x reference)
#include <cuda_runtime.h>
#include <cstdint>

#define D_DIM 4096
#define K_SEL 2048
#define NT    512
#define FULL  0xFFFFFFFFu
#define CAP   448
#define MAXA  6
#define MAXP  6
#define WLO  (-0.10f)
#define WHI  ( 0.10f)
#define NEG_INF __int_as_float(0xff800000)

// warp 0 only: exact rank jrank (1-based from top) among m (<=64) values in buf
__device__ __forceinline__ void rank64(const float* buf, int m, int jrank,
                                       int lane, float* s_T) {
    float g0 = (lane      < m) ? buf[lane]      : NEG_INF;
    float g1 = (lane + 32 < m) ? buf[lane + 32] : NEG_INF;
    int gt0 = 0, eq0 = 0, gt1 = 0, eq1 = 0;
#pragma unroll
    for (int d = 0; d < 32; d++) {
        float o0 = __shfl_sync(FULL, g0, d);
        float o1 = __shfl_sync(FULL, g1, d);
        gt0 += (o0 > g0) + (o1 > g0);
        eq0 += (o0 == g0) + (o1 == g0);   // eq includes self
        gt1 += (o0 > g1) + (o1 > g1);
        eq1 += (o0 == g1) + (o1 == g1);
    }
    if (lane      < m && gt0 < jrank && gt0 + eq0 >= jrank) *s_T = g0;
    if (lane + 32 < m && gt1 < jrank && gt1 + eq1 >= jrank) *s_T = g1;
}

__device__ __forceinline__ void cpa16(uint32_t saddr, const void* g) {
    asm volatile("cp.async.cg.shared.global [%0], [%1], 16;\n"
                 :: "r"(saddr), "l"(g) : "memory");
}
__device__ __forceinline__ void cp_commit() {
    asm volatile("cp.async.commit_group;\n" ::: "memory");
}
__device__ __forceinline__ void cp_wait0() {
    asm volatile("cp.async.wait_group 0;\n" ::: "memory");
}

__global__ __launch_bounds__(NT, 4)
void topk_mask_kernel(const float* __restrict__ x, float* __restrict__ out,
                      int rows) {
    __shared__ float4 stg[2][D_DIM / 4];    // 2 x 16 KB row staging
    __shared__ float  buf[CAP];
    __shared__ float  gbuf[64];
    __shared__ int    s_cb[MAXA], s_m[MAXA], s_p[MAXP], s_g;
    __shared__ float  s_T;

    const int tid  = threadIdx.x;
    const int lane = tid & 31;
    const int stride = gridDim.x;
    const uint32_t sb0 = (uint32_t)__cvta_generic_to_shared(&stg[0][0]);
    const uint32_t sb1 = (uint32_t)__cvta_generic_to_shared(&stg[1][0]);

    // ---- prologue: prefetch first two rows ----
    {
        const float4* g0 = (const float4*)(x + (size_t)blockIdx.x * D_DIM);
        cpa16(sb0 + tid * 16u, g0 + tid);
        cpa16(sb0 + (NT + tid) * 16u, g0 + NT + tid);
        cp_commit();
        int r1 = blockIdx.x + stride;
        if (r1 < rows) {
            const float4* g1 = (const float4*)(x + (size_t)r1 * D_DIM);
            cpa16(sb1 + tid * 16u, g1 + tid);
            cpa16(sb1 + (NT + tid) * 16u, g1 + NT + tid);
            cp_commit();
        }
    }
    if (tid < MAXA) { s_cb[tid] = 0; s_m[tid] = 0; }
    if (tid < MAXP) s_p[tid] = 0;
    if (tid == NT - 1) s_g = 0;

    float  Tprev = 0.0f;
    int    havePrev = 0;
    size_t prevRow = 0;
    int    cur = 0;

#pragma unroll 1
    for (int row = blockIdx.x; row < rows; row += stride, cur ^= 1) {
        cp_wait0();
        __syncthreads();            // stg[cur] = row data; counter zeros visible

        float4 v0 = stg[cur][tid];
        float4 v1 = stg[cur][NT + tid];
        float vals[8] = { v0.x, v0.y, v0.z, v0.w, v1.x, v1.y, v1.z, v1.w };

        float wlo = WLO, whi = WHI;
        float blo = -64.0f, bhi = 64.0f;
        int   cblo = D_DIM, cbhi = 0;
        int   solved = 0, CB = 0, M = 0;

#pragma unroll 1
        for (int at = 0; at < MAXA; at++) {
            // ---- capture: exact count(>= whi) + push values in [wlo, whi) ----
            int cb = 0;
#pragma unroll
            for (int i = 0; i < 8; i++) {
                float v = vals[i];
                bool pb = (v >= whi);
                cb += pb;
                if (v >= wlo && !pb) {
                    int p = atomicAdd(&s_m[at], 1);
                    if (p < CAP) buf[p] = v;
                }
            }
            cb = __reduce_add_sync(FULL, cb);
            if (lane == 0) atomicAdd(&s_cb[at], cb);

            // ---- overlapped: mask + store PREVIOUS row from its staging ----
            if (at == 0 && havePrev) {
                float4 a0 = stg[cur ^ 1][tid];
                float4 a1 = stg[cur ^ 1][NT + tid];
                float4 w0, w1;
                w0.x = (a0.x >= Tprev) ? a0.x : 0.0f;
                w0.y = (a0.y >= Tprev) ? a0.y : 0.0f;
                w0.z = (a0.z >= Tprev) ? a0.z : 0.0f;
                w0.w = (a0.w >= Tprev) ? a0.w : 0.0f;
                w1.x = (a1.x >= Tprev) ? a1.x : 0.0f;
                w1.y = (a1.y >= Tprev) ? a1.y : 0.0f;
                w1.z = (a1.z >= Tprev) ? a1.z : 0.0f;
                w1.w = (a1.w >= Tprev) ? a1.w : 0.0f;
                float4* o = (float4*)(out + prevRow * (size_t)D_DIM);
                __stcs(o + tid, w0);
                __stcs(o + NT + tid, w1);
            }
            __syncthreads();        // counts final; prev-row staging consumed
            CB = s_cb[at];
            M  = s_m[at];

            // ---- prefetch next row into the buffer just freed by the mask ----
            if (at == 0) {
                int nr = row + stride;
                if (havePrev && nr < rows) {
                    const float4* g = (const float4*)(x + (size_t)nr * D_DIM);
                    uint32_t sbn = cur ? sb0 : sb1;   // stg[cur^1]
                    cpa16(sbn + tid * 16u, g + tid);
                    cpa16(sbn + (NT + tid) * 16u, g + NT + tid);
                    cp_commit();
                }
            }

            if (CB < K_SEL && K_SEL <= CB + M && M <= CAP) { solved = 1; break; }

            // ---- window missed (p < 1e-6): exact bracket update, retry ----
            int CA = CB + M;
            if (CB >= K_SEL)      { blo = whi; cblo = CB; }
            else if (CA < K_SEL)  { bhi = wlo; cbhi = CA; }
            else                  { blo = wlo; cblo = CA; bhi = whi; cbhi = CB; }
            int live = cblo - cbhi;
            if (live <= CAP) { wlo = blo; whi = bhi; }
            else {
                float t  = ((float)(cblo - K_SEL) + 0.5f) / (float)live;
                float tc = blo + t * (bhi - blo);
                float hw = (bhi - blo) * (150.0f / (float)live);
                wlo = fmaxf(blo, tc - hw);
                whi = fminf(bhi, tc + hw);
                if (!(wlo < whi)) { wlo = blo; whi = bhi; }
            }
        }

        if (solved) {
            // candidates sit one-per-thread: refinement probes are 3 inst each
            const int r = K_SEL - CB;
            float plo = wlo, phi = whi;
            int c_lo = M, c_hi = 0;
            int pi = 0, okp = 1;
            while (c_lo - c_hi > 64) {
                if (pi >= MAXP) { okp = 0; break; }
                float t = (float)(r - c_hi) / (float)(c_lo - c_hi);
                t = fminf(fmaxf(t, 0.04f), 0.96f);
                float mid = phi - t * (phi - plo);
                if (!(mid > plo && mid < phi)) { okp = 0; break; }
                int c = (tid < M) ? (buf[tid] >= mid) : 0;
                c = __reduce_add_sync(FULL, c);
                if (lane == 0) atomicAdd(&s_p[pi], c);
                __syncthreads();
                c = s_p[pi]; pi++;
                if (c >= r) { plo = mid; c_lo = c; }
                else        { phi = mid; c_hi = c; }
            }
            if (okp) {
                if (tid < M) {
                    float v = buf[tid];
                    if (v >= plo && v < phi) {
                        int p = atomicAdd(&s_g, 1);
                        if (p < 64) gbuf[p] = v;
                    }
                }
                __syncthreads();
                if (tid < 32) rank64(gbuf, c_lo - c_hi, r - c_hi, lane, &s_T);
            } else {
                if (tid == 0) s_T = plo;   // tie-collapse safety net
            }
        } else {
            if (tid == 0) s_T = blo;       // unreachable in practice
        }
        __syncthreads();                   // s_T ready; all counter reads done
        Tprev = s_T;
        havePrev = 1;
        prevRow = row;

        // zero counters for the next row (visible after next top barrier)
        if (tid < MAXA) { s_cb[tid] = 0; s_m[tid] = 0; }
        if (tid < MAXP) s_p[tid] = 0;
        if (tid == NT - 1) s_g = 0;
    }

    // ---- epilogue: mask the final row ----
    if (havePrev) {
        float4 a0 = stg[cur ^ 1][tid];
        float4 a1 = stg[cur ^ 1][NT + tid];
        float4 w0, w1;
        w0.x = (a0.x >= Tprev) ? a0.x : 0.0f;
        w0.y = (a0.y >= Tprev) ? a0.y : 0.0f;
        w0.z = (a0.z >= Tprev) ? a0.z : 0.0f;
        w0.w = (a0.w >= Tprev) ? a0.w : 0.0f;
        w1.x = (a1.x >= Tprev) ? a1.x : 0.0f;
        w1.y = (a1.y >= Tprev) ? a1.y : 0.0f;
        w1.z = (a1.z >= Tprev) ? a1.z : 0.0f;
        w1.w = (a1.w >= Tprev) ? a1.w : 0.0f;
        float4* o = (float4*)(out + prevRow * (size_t)D_DIM);
        __stcs(o + tid, w0);
        __stcs(o + NT + tid, w1);
    }
}

extern "C" void kernel_launch(void* const* d_in, const int* in_sizes, int n_in,
                              void* d_out, int out_size) {
    const float* x = (const float*)d_in[0];
    float* out = (float*)d_out;
    int rows = in_sizes[0] / D_DIM;       // 16384 for (4, 4096, 4096)

    int dev = 0;
    cudaGetDevice(&dev);
    int sms = 148;
    cudaDeviceGetAttribute(&sms, cudaDevAttrMultiProcessorCount, dev);
    int grid = sms * 4;                   // 4 persistent CTAs per SM
    if (grid > rows) grid = rows;
    topk_mask_kernel<<<grid, NT>>>(x, out, rows);
}

// round 8
// speedup vs baseline: 1.6323x; 1.6323x over previous
#include <cuda_runtime.h>
#include <cstdint>

#define D_DIM 4096
#define K_SEL 2048
#define NT    128
#define EPT   32
#define NV4   8
#define FULL  0xFFFFFFFFu
#define CAP   64
#define MAXIT 12
#define NEG_INF __int_as_float(0xff800000)
#define INV_DENS 0.000611995f   // 1 / (4096 * phi(0)) = 1/1634

// warp 0 only: exact rank jrank (1-based from top) among m (<=64) values in buf
__device__ __forceinline__ void rank64(const float* buf, int m, int jrank,
                                       int lane, float* s_T) {
    float g0 = (lane      < m) ? buf[lane]      : NEG_INF;
    float g1 = (lane + 32 < m) ? buf[lane + 32] : NEG_INF;
    int gt0 = 0, eq0 = 0, gt1 = 0, eq1 = 0;
#pragma unroll
    for (int d = 0; d < 32; d++) {
        float o0 = __shfl_sync(FULL, g0, d);
        float o1 = __shfl_sync(FULL, g1, d);
        gt0 += (o0 > g0) + (o1 > g0);
        eq0 += (o0 == g0) + (o1 == g0);   // eq includes self
        gt1 += (o0 > g1) + (o1 > g1);
        eq1 += (o0 == g1) + (o1 == g1);
    }
    if (lane      < m && gt0 < jrank && gt0 + eq0 >= jrank) *s_T = g0;
    if (lane + 32 < m && gt1 < jrank && gt1 + eq1 >= jrank) *s_T = g1;
}

__global__ __launch_bounds__(NT, 12)
void topk_mask_kernel(const float* __restrict__ x, float* __restrict__ out) {
    __shared__ int   s_c0;
    __shared__ int   s_cb[MAXIT];   // exact count(>= tb) per iteration
    __shared__ int   s_mm[MAXIT];   // capture count per iteration
    __shared__ float gbuf[CAP];
    __shared__ float s_T;

    const int tid  = threadIdx.x;
    const int lane = tid & 31;
    const size_t row = blockIdx.x;

    const float4* xin  = reinterpret_cast<const float4*>(x   + row * (size_t)D_DIM);
    float4*       xout = reinterpret_cast<float4*>      (out + row * (size_t)D_DIM);

    if (tid < MAXIT) { s_cb[tid] = 0; s_mm[tid] = 0; }
    if (tid == MAXIT) s_c0 = 0;
    __syncthreads();

    // ---- load 32 elements per thread (8x coalesced float4, streaming) ----
    float vals[EPT];
#pragma unroll
    for (int i = 0; i < NV4; i++) {
        float4 v = __ldcs(xin + i * NT + tid);
        vals[4*i+0] = v.x; vals[4*i+1] = v.y;
        vals[4*i+2] = v.z; vals[4*i+3] = v.w;
    }

    // ---- Pass A: c0 = count(x >= 0); locates the median statistically ----
    {
        int c = 0;
#pragma unroll
        for (int i = 0; i < EPT; i++) c += (vals[i] >= 0.0f);
        c = __reduce_add_sync(FULL, c);
        if (lane == 0) atomicAdd(&s_c0, c);
    }
    __syncthreads();
    const int c0 = s_c0;

    // ---- initial bracket + density-model window guess ----
    float lo, hi; int clo, chiv;
    float jf, dirv;
    if (c0 >= K_SEL) {
        lo = 0.0f;  clo = c0;    hi = 8.0f; chiv = 0;
        jf = (float)(c0 - K_SEL); dirv = 1.0f;
    } else {
        lo = -8.0f; clo = D_DIM; hi = 0.0f; chiv = c0;
        jf = (float)(K_SEL - c0); dirv = -1.0f;
    }
    float tc = dirv * jf * INV_DENS;
    float dl = fmaf(jf, 0.10f, 20.0f) * INV_DENS;
    float ta = tc - dl, tb = tc + dl;

    int solved = 0;
#pragma unroll 1
    for (int it = 0; it < MAXIT; it++) {
        ta = fmaxf(ta, lo); tb = fminf(tb, hi);
        if (!(ta < tb)) { ta = lo; tb = hi; }

        // ---- capture pass: exact count(>= tb) + push values in [ta, tb) ----
        int cb = 0;
#pragma unroll
        for (int i = 0; i < EPT; i++) {
            float v = vals[i];
            bool pb = (v >= tb);
            cb += pb;
            if ((v >= ta) && !pb) {
                int p = atomicAdd(&s_mm[it], 1);
                if (p < CAP) gbuf[p] = v;
            }
        }
        cb = __reduce_add_sync(FULL, cb);
        if (lane == 0) atomicAdd(&s_cb[it], cb);
        __syncthreads();

        const int CB = s_cb[it];          // exact count(>= tb)
        const int M  = s_mm[it];          // exact count in [ta, tb)
        if (CB < K_SEL && K_SEL <= CB + M && M <= CAP) {
            if (tid < 32) rank64(gbuf, M, K_SEL - CB, lane, &s_T);
            __syncthreads();
            solved = 1;
            break;
        }

        // ---- guess missed (rare): shrink bracket with the exact counts ----
        const int CA = CB + M;            // exact count(>= ta)
        if (CB >= K_SEL)      { lo = tb; clo = CB; }
        else if (CA < K_SEL)  { hi = ta; chiv = CA; }
        else                  { lo = ta; clo = CA; hi = tb; chiv = CB; } // overflow
        float span = hi - lo;
        float live = fmaxf((float)(clo - chiv), 1.0f);
        float fr   = ((float)(clo - K_SEL) + 0.5f) / live;
        tc = fmaf(fr, span, lo);
        dl = (span / live) * 20.0f;
        ta = tc - dl; tb = tc + dl;
    }

    if (!solved) {                        // never in practice: safety net
        if (tid == 0) s_T = lo;
        __syncthreads();
    }
    const float tf = s_T;

    // ---- apply mask and stream out ----
#pragma unroll
    for (int i = 0; i < NV4; i++) {
        float4 w;
        w.x = (vals[4*i+0] >= tf) ? vals[4*i+0] : 0.0f;
        w.y = (vals[4*i+1] >= tf) ? vals[4*i+1] : 0.0f;
        w.z = (vals[4*i+2] >= tf) ? vals[4*i+2] : 0.0f;
        w.w = (vals[4*i+3] >= tf) ? vals[4*i+3] : 0.0f;
        __stcs(xout + i * NT + tid, w);
    }
}

extern "C" void kernel_launch(void* const* d_in, const int* in_sizes, int n_in,
                              void* d_out, int out_size) {
    const float* x = (const float*)d_in[0];
    float* out = (float*)d_out;
    int rows = in_sizes[0] / D_DIM;       // 16384 for (4, 4096, 4096)
    topk_mask_kernel<<<rows, NT>>>(x, out);
}